// round 2
// baseline (speedup 1.0000x reference)
#include <cuda_runtime.h>
#include <cuda_bf16.h>
#include <math.h>

// Problem constants
#define T_TOK 8192
#define HID   1024
#define NEXP  64
#define KTOP  2
#define CAP   1024
#define FFN   512
#define SFFN  1024
#define NASSIGN (T_TOK*KTOP)

// ---------------- scratch (device globals; no allocation allowed) -------------
__device__ float g_logits[T_TOK * NEXP];          // 2 MB
__device__ int   g_topi[NASSIGN];
__device__ float g_topv[NASSIGN];
__device__ int   g_counts[NEXP];
__device__ int   g_listcnt[NEXP];
__device__ float g_psum[NEXP];
__device__ int   g_assign[NEXP * CAP];            // assignment id per (expert, slot)
__device__ int   g_slot[NASSIGN];                 // slot within expert, -1 if dropped
__device__ float g_hbuf[(size_t)NEXP * CAP * FFN];   // 128 MB
__device__ float g_eout[(size_t)NEXP * CAP * HID];   // 256 MB
__device__ float g_sbuf[(size_t)T_TOK * SFFN];       // 32 MB

__device__ __forceinline__ float gelu_f(float x) {
    // jax.nn.gelu default (approximate=True, tanh form)
    float x3 = x * x * x;
    return 0.5f * x * (1.0f + tanhf(0.7978845608028654f * (x + 0.044715f * x3)));
}

// ---------------- zero bookkeeping ----------------
__global__ void zero_kernel() {
    int i = threadIdx.x;
    if (i < NEXP) { g_counts[i] = 0; g_listcnt[i] = 0; g_psum[i] = 0.0f; }
}

// ---------------- generic 64x64 tiled SGEMM  C = [gelu](A @ B) ----------------
// A: MxK (lda), B: KxN row-major (ldb), C: MxN (ldc). N%64==0, K%16==0.
#define TM 64
#define TN 64
#define TKK 16

template<bool DOGELU>
__global__ void sgemm_plain(const float* __restrict__ A, const float* __restrict__ B,
                            float* __restrict__ Cc, int M, int N, int Kd,
                            int lda, int ldb, int ldc)
{
    __shared__ float As[TKK][TM + 4];
    __shared__ float Bs[TKK][TN];
    int tid = threadIdx.x;
    int tx = tid & 15, ty = tid >> 4;
    int bm = blockIdx.y * TM, bn = blockIdx.x * TN;

    int la_m = tid >> 2;
    int la_k = (tid & 3) * 4;
    int lb_k = tid >> 4;
    int lb_n = (tid & 15) * 4;

    float acc[4][4];
#pragma unroll
    for (int i = 0; i < 4; i++)
#pragma unroll
        for (int j = 0; j < 4; j++) acc[i][j] = 0.0f;

    for (int k0 = 0; k0 < Kd; k0 += TKK) {
        int gm = bm + la_m;
        float4 av = make_float4(0.f, 0.f, 0.f, 0.f);
        if (gm < M) av = *reinterpret_cast<const float4*>(A + (size_t)gm * lda + k0 + la_k);
        As[la_k + 0][la_m] = av.x;
        As[la_k + 1][la_m] = av.y;
        As[la_k + 2][la_m] = av.z;
        As[la_k + 3][la_m] = av.w;
        float4 bv = *reinterpret_cast<const float4*>(B + (size_t)(k0 + lb_k) * ldb + bn + lb_n);
        Bs[lb_k][lb_n + 0] = bv.x;
        Bs[lb_k][lb_n + 1] = bv.y;
        Bs[lb_k][lb_n + 2] = bv.z;
        Bs[lb_k][lb_n + 3] = bv.w;
        __syncthreads();
#pragma unroll
        for (int kk = 0; kk < TKK; kk++) {
            float a[4], b[4];
#pragma unroll
            for (int i = 0; i < 4; i++) a[i] = As[kk][ty * 4 + i];
#pragma unroll
            for (int j = 0; j < 4; j++) b[j] = Bs[kk][tx * 4 + j];
#pragma unroll
            for (int i = 0; i < 4; i++)
#pragma unroll
                for (int j = 0; j < 4; j++) acc[i][j] += a[i] * b[j];
        }
        __syncthreads();
    }
#pragma unroll
    for (int i = 0; i < 4; i++) {
        int gm = bm + ty * 4 + i;
        if (gm >= M) continue;
#pragma unroll
        for (int j = 0; j < 4; j++) {
            float v = acc[i][j];
            if (DOGELU) v = gelu_f(v);
            Cc[(size_t)gm * ldc + bn + tx * 4 + j] = v;
        }
    }
}

// ---------------- router top-k / softmax / counts ----------------
__global__ void topk_kernel() {
    int warp = threadIdx.x >> 5, lane = threadIdx.x & 31;
    int t = blockIdx.x * 4 + warp;
    if (t >= T_TOK) return;
    float s0 = g_logits[t * NEXP + lane];
    float s1 = g_logits[t * NEXP + 32 + lane];
    float m = fmaxf(s0, s1);
#pragma unroll
    for (int o = 16; o; o >>= 1) m = fmaxf(m, __shfl_xor_sync(0xffffffffu, m, o));
    float e0 = expf(s0 - m), e1 = expf(s1 - m);
    float d = e0 + e1;
#pragma unroll
    for (int o = 16; o; o >>= 1) d += __shfl_xor_sync(0xffffffffu, d, o);
    float p0 = e0 / d, p1 = e1 / d;

    // top-1 (ties -> lowest index, matching jax top_k)
    float loc = fmaxf(p0, p1);
    float mx = loc;
#pragma unroll
    for (int o = 16; o; o >>= 1) mx = fmaxf(mx, __shfl_xor_sync(0xffffffffu, mx, o));
    int cand = 0x7fffffff;
    if (p0 == mx) cand = lane;
    if (p1 == mx) cand = min(cand, lane + 32);
#pragma unroll
    for (int o = 16; o; o >>= 1) cand = min(cand, __shfl_xor_sync(0xffffffffu, cand, o));
    int i1 = cand;
    float v1 = mx;

    // top-2 excluding i1
    float q0 = (lane == i1) ? -1e30f : p0;
    float q1 = (lane + 32 == i1) ? -1e30f : p1;
    float loc2 = fmaxf(q0, q1);
    float mx2 = loc2;
#pragma unroll
    for (int o = 16; o; o >>= 1) mx2 = fmaxf(mx2, __shfl_xor_sync(0xffffffffu, mx2, o));
    int cand2 = 0x7fffffff;
    if (q0 == mx2) cand2 = lane;
    if (q1 == mx2) cand2 = min(cand2, lane + 32);
#pragma unroll
    for (int o = 16; o; o >>= 1) cand2 = min(cand2, __shfl_xor_sync(0xffffffffu, cand2, o));
    int i2 = cand2;
    float v2 = mx2;

    if (lane == 0) {
        g_topi[t * 2 + 0] = i1; g_topv[t * 2 + 0] = v1;
        g_topi[t * 2 + 1] = i2; g_topv[t * 2 + 1] = v2;
        atomicAdd(&g_counts[i1], 1);
        atomicAdd(&g_counts[i2], 1);
    }
    atomicAdd(&g_psum[lane], p0);
    atomicAdd(&g_psum[lane + 32], p1);
}

// ---------------- build per-expert slot lists ----------------
__global__ void build_kernel() {
    int a = blockIdx.x * blockDim.x + threadIdx.x;
    if (a >= NASSIGN) return;
    int e = g_topi[a];
    int pos = atomicAdd(&g_listcnt[e], 1);
    if (pos < CAP) {
        g_assign[e * CAP + pos] = a;
        g_slot[a] = pos;
    } else {
        g_slot[a] = -1;
    }
}

// ---------------- expert GEMM 1: h = gelu( gather(x) @ w1[e] ) ----------------
__global__ void expert_gemm1(const float* __restrict__ x, const float* __restrict__ w1)
{
    int e = blockIdx.z;
    int cnt = min(g_listcnt[e], CAP);
    int bm = blockIdx.y * TM;
    if (bm >= cnt) return;
    int bn = blockIdx.x * TN;
    const float* B = w1 + (size_t)e * HID * FFN;
    float* Cc = g_hbuf + (size_t)e * CAP * FFN;
    const int* assign = g_assign + e * CAP;

    __shared__ float As[TKK][TM + 4];
    __shared__ float Bs[TKK][TN];
    int tid = threadIdx.x;
    int tx = tid & 15, ty = tid >> 4;
    int la_m = tid >> 2;
    int la_k = (tid & 3) * 4;
    int lb_k = tid >> 4;
    int lb_n = (tid & 15) * 4;

    int gm = bm + la_m;
    int token = -1;
    if (gm < cnt) token = assign[gm] >> 1;   // KTOP == 2

    float acc[4][4];
#pragma unroll
    for (int i = 0; i < 4; i++)
#pragma unroll
        for (int j = 0; j < 4; j++) acc[i][j] = 0.0f;

    for (int k0 = 0; k0 < HID; k0 += TKK) {
        float4 av = make_float4(0.f, 0.f, 0.f, 0.f);
        if (token >= 0) av = *reinterpret_cast<const float4*>(x + (size_t)token * HID + k0 + la_k);
        As[la_k + 0][la_m] = av.x;
        As[la_k + 1][la_m] = av.y;
        As[la_k + 2][la_m] = av.z;
        As[la_k + 3][la_m] = av.w;
        float4 bv = *reinterpret_cast<const float4*>(B + (size_t)(k0 + lb_k) * FFN + bn + lb_n);
        Bs[lb_k][lb_n + 0] = bv.x;
        Bs[lb_k][lb_n + 1] = bv.y;
        Bs[lb_k][lb_n + 2] = bv.z;
        Bs[lb_k][lb_n + 3] = bv.w;
        __syncthreads();
#pragma unroll
        for (int kk = 0; kk < TKK; kk++) {
            float a[4], b[4];
#pragma unroll
            for (int i = 0; i < 4; i++) a[i] = As[kk][ty * 4 + i];
#pragma unroll
            for (int j = 0; j < 4; j++) b[j] = Bs[kk][tx * 4 + j];
#pragma unroll
            for (int i = 0; i < 4; i++)
#pragma unroll
                for (int j = 0; j < 4; j++) acc[i][j] += a[i] * b[j];
        }
        __syncthreads();
    }
#pragma unroll
    for (int i = 0; i < 4; i++) {
        int rm = bm + ty * 4 + i;
        if (rm >= cnt) continue;
#pragma unroll
        for (int j = 0; j < 4; j++)
            Cc[(size_t)rm * FFN + bn + tx * 4 + j] = gelu_f(acc[i][j]);
    }
}

// ---------------- expert GEMM 2: eout = h @ w2[e] ----------------
__global__ void expert_gemm2(const float* __restrict__ w2)
{
    int e = blockIdx.z;
    int cnt = min(g_listcnt[e], CAP);
    int bm = blockIdx.y * TM;
    if (bm >= cnt) return;
    int bn = blockIdx.x * TN;
    const float* A = g_hbuf + (size_t)e * CAP * FFN;
    const float* B = w2 + (size_t)e * FFN * HID;
    float* Cc = g_eout + (size_t)e * CAP * HID;

    __shared__ float As[TKK][TM + 4];
    __shared__ float Bs[TKK][TN];
    int tid = threadIdx.x;
    int tx = tid & 15, ty = tid >> 4;
    int la_m = tid >> 2;
    int la_k = (tid & 3) * 4;
    int lb_k = tid >> 4;
    int lb_n = (tid & 15) * 4;

    float acc[4][4];
#pragma unroll
    for (int i = 0; i < 4; i++)
#pragma unroll
        for (int j = 0; j < 4; j++) acc[i][j] = 0.0f;

    for (int k0 = 0; k0 < FFN; k0 += TKK) {
        int gm = bm + la_m;
        float4 av = make_float4(0.f, 0.f, 0.f, 0.f);
        if (gm < cnt) av = *reinterpret_cast<const float4*>(A + (size_t)gm * FFN + k0 + la_k);
        As[la_k + 0][la_m] = av.x;
        As[la_k + 1][la_m] = av.y;
        As[la_k + 2][la_m] = av.z;
        As[la_k + 3][la_m] = av.w;
        float4 bv = *reinterpret_cast<const float4*>(B + (size_t)(k0 + lb_k) * HID + bn + lb_n);
        Bs[lb_k][lb_n + 0] = bv.x;
        Bs[lb_k][lb_n + 1] = bv.y;
        Bs[lb_k][lb_n + 2] = bv.z;
        Bs[lb_k][lb_n + 3] = bv.w;
        __syncthreads();
#pragma unroll
        for (int kk = 0; kk < TKK; kk++) {
            float a[4], b[4];
#pragma unroll
            for (int i = 0; i < 4; i++) a[i] = As[kk][ty * 4 + i];
#pragma unroll
            for (int j = 0; j < 4; j++) b[j] = Bs[kk][tx * 4 + j];
#pragma unroll
            for (int i = 0; i < 4; i++)
#pragma unroll
                for (int j = 0; j < 4; j++) acc[i][j] += a[i] * b[j];
        }
        __syncthreads();
    }
#pragma unroll
    for (int i = 0; i < 4; i++) {
        int rm = bm + ty * 4 + i;
        if (rm >= cnt) continue;
#pragma unroll
        for (int j = 0; j < 4; j++)
            Cc[(size_t)rm * HID + bn + tx * 4 + j] = acc[i][j];
    }
}

// ---------------- combine: out[t] = shared(out already) + sum_k p*eout ----------------
__global__ void combine_kernel(float* __restrict__ out)
{
    int t = blockIdx.x;
    int a0 = t * 2, a1 = a0 + 1;
    int e0 = g_topi[a0], e1 = g_topi[a1];
    float p0 = g_topv[a0], p1 = g_topv[a1];
    int j0 = g_slot[a0], j1 = g_slot[a1];
    const float* r0 = g_eout + ((size_t)e0 * CAP + (j0 < 0 ? 0 : j0)) * HID;
    const float* r1 = g_eout + ((size_t)e1 * CAP + (j1 < 0 ? 0 : j1)) * HID;
    for (int h = threadIdx.x; h < HID; h += blockDim.x) {
        float v = out[(size_t)t * HID + h];
        if (j0 >= 0) v += p0 * r0[h];
        if (j1 >= 0) v += p1 * r1[h];
        out[(size_t)t * HID + h] = v;
    }
}

// ---------------- aux loss ----------------
__global__ void aux_kernel(float* __restrict__ out, int out_size)
{
    __shared__ float vals[NEXP];
    int i = threadIdx.x;
    if (i < NEXP) {
        float f = (float)g_counts[i] / (float)(T_TOK * KTOP);
        float P = g_psum[i] / (float)T_TOK;
        vals[i] = f * P;
    }
    __syncthreads();
    if (i == 0) {
        float s = 0.0f;
        for (int j = 0; j < NEXP; j++) s += vals[j];
        if (out_size > T_TOK * HID) out[T_TOK * HID] = 0.01f * (float)NEXP * s;
    }
}

// ---------------- launch ----------------
extern "C" void kernel_launch(void* const* d_in, const int* in_sizes, int n_in,
                              void* d_out, int out_size)
{
    const float* x        = (const float*)d_in[0];  // [T,H]
    const float* w_router = (const float*)d_in[1];  // [H,E]
    const float* w1       = (const float*)d_in[2];  // [E,H,F]
    const float* w2       = (const float*)d_in[3];  // [E,F,H]
    const float* ws1      = (const float*)d_in[4];  // [H,SF]
    const float* ws2      = (const float*)d_in[5];  // [SF,H]
    float* out = (float*)d_out;

    float* logits; cudaGetSymbolAddress((void**)&logits, g_logits);
    float* sbuf;   cudaGetSymbolAddress((void**)&sbuf, g_sbuf);

    zero_kernel<<<1, 256>>>();

    // router logits: [T,E] = x @ w_router
    sgemm_plain<false><<<dim3(NEXP / TN, T_TOK / TM), 256>>>(
        x, w_router, logits, T_TOK, NEXP, HID, HID, NEXP, NEXP);

    topk_kernel<<<T_TOK / 4, 128>>>();
    build_kernel<<<(NASSIGN + 255) / 256, 256>>>();

    expert_gemm1<<<dim3(FFN / TN, CAP / TM, NEXP), 256>>>(x, w1);
    expert_gemm2<<<dim3(HID / TN, CAP / TM, NEXP), 256>>>(w2);

    // shared expert
    sgemm_plain<true><<<dim3(SFFN / TN, T_TOK / TM), 256>>>(
        x, ws1, sbuf, T_TOK, SFFN, HID, HID, SFFN, SFFN);
    sgemm_plain<false><<<dim3(HID / TN, T_TOK / TM), 256>>>(
        sbuf, ws2, out, T_TOK, HID, SFFN, SFFN, HID, HID);

    combine_kernel<<<T_TOK, 256>>>(out);
    aux_kernel<<<1, 64>>>(out, out_size);
}

// round 4
// speedup vs baseline: 3.3620x; 3.3620x over previous
#include <cuda_runtime.h>
#include <cuda_bf16.h>
#include <math.h>
#include <stdint.h>

// ---------------- problem constants ----------------
#define T_TOK 8192
#define HID   1024
#define NEXP  64
#define KTOP  2
#define CAP   1024
#define FFN   512
#define SFFN  1024
#define NASSIGN (T_TOK*KTOP)

// ---------------- helpers (compute_103-safe PTX only) ----------------
__device__ __forceinline__ uint32_t smem_u32(const void* p) {
    uint32_t a;
    asm("{ .reg .u64 t; cvta.to.shared.u64 t, %1; cvt.u32.u64 %0, t; }" : "=r"(a) : "l"(p));
    return a;
}
__device__ __forceinline__ void ldm_x4(uint32_t addr, uint32_t& r0, uint32_t& r1,
                                       uint32_t& r2, uint32_t& r3) {
    asm volatile("ldmatrix.sync.aligned.m8n8.x4.shared.b16 {%0,%1,%2,%3}, [%4];"
        : "=r"(r0), "=r"(r1), "=r"(r2), "=r"(r3) : "r"(addr));
}
__device__ __forceinline__ void mma_bf16(float* d, const uint32_t* a, const uint32_t* b) {
    asm volatile("mma.sync.aligned.m16n8k16.row.col.f32.bf16.bf16.f32 "
        "{%0,%1,%2,%3}, {%4,%5,%6,%7}, {%8,%9}, {%0,%1,%2,%3};"
        : "+f"(d[0]), "+f"(d[1]), "+f"(d[2]), "+f"(d[3])
        : "r"(a[0]), "r"(a[1]), "r"(a[2]), "r"(a[3]), "r"(b[0]), "r"(b[1]));
}
__device__ __forceinline__ void cp16(uint32_t dst, const void* src) {
    size_t g = __cvta_generic_to_global(src);
    asm volatile("cp.async.cg.shared.global [%0], [%1], 16;" :: "r"(dst), "l"(g));
}
#define CP_COMMIT() asm volatile("cp.async.commit_group;" ::: "memory")
#define CP_WAIT1()  asm volatile("cp.async.wait_group 1;" ::: "memory")
// SW64-style swizzle: xor 16B-chunk index (bits 4-5) with bits 7-8 (row>>1)
#define SWZ(o) ((o) ^ (((o) >> 3) & 0x30))

// ---------------- scratch (device globals; allocation is forbidden) ----------
__device__ float g_logits[T_TOK * NEXP];
__device__ int   g_topi[NASSIGN];
__device__ float g_topv[NASSIGN];
__device__ int   g_counts[NEXP];
__device__ int   g_listcnt[NEXP];
__device__ float g_psum[NEXP];
__device__ int   g_assign[NEXP * CAP];
__device__ int   g_slot[NASSIGN];
__device__ float g_eout[(size_t)NEXP * CAP * HID];

__device__ __align__(16) __nv_bfloat16 g_xhi[T_TOK * HID];
__device__ __align__(16) __nv_bfloat16 g_xlo[T_TOK * HID];
__device__ __align__(16) __nv_bfloat16 g_w1th[(size_t)NEXP * FFN * HID];
__device__ __align__(16) __nv_bfloat16 g_w1tl[(size_t)NEXP * FFN * HID];
__device__ __align__(16) __nv_bfloat16 g_w2th[(size_t)NEXP * HID * FFN];
__device__ __align__(16) __nv_bfloat16 g_w2tl[(size_t)NEXP * HID * FFN];
__device__ __align__(16) __nv_bfloat16 g_ws1th[(size_t)SFFN * HID];
__device__ __align__(16) __nv_bfloat16 g_ws1tl[(size_t)SFFN * HID];
__device__ __align__(16) __nv_bfloat16 g_ws2th[(size_t)HID * SFFN];
__device__ __align__(16) __nv_bfloat16 g_ws2tl[(size_t)HID * SFFN];
__device__ __align__(16) __nv_bfloat16 g_hh[(size_t)NEXP * CAP * FFN];
__device__ __align__(16) __nv_bfloat16 g_hl[(size_t)NEXP * CAP * FFN];
__device__ __align__(16) __nv_bfloat16 g_sh[(size_t)T_TOK * SFFN];
__device__ __align__(16) __nv_bfloat16 g_sl[(size_t)T_TOK * SFFN];

__device__ __forceinline__ float gelu_f(float x) {
    float x3 = x * x * x;
    return 0.5f * x * (1.0f + tanhf(0.7978845608028654f * (x + 0.044715f * x3)));
}

// ---------------- prepass: elementwise fp32 -> bf16 hi/lo split ----------------
__global__ void csplit(const float* __restrict__ in, __nv_bfloat16* __restrict__ oh,
                       __nv_bfloat16* __restrict__ ol, int n) {
    for (int i = blockIdx.x * blockDim.x + threadIdx.x; i < n; i += gridDim.x * blockDim.x) {
        float v = in[i];
        __nv_bfloat16 h = __float2bfloat16(v);
        oh[i] = h;
        ol[i] = __float2bfloat16(v - __bfloat162float(h));
    }
}

// ---------------- prepass: batched transpose + split: in[z][R][C] -> out[z][C][R] ----
__global__ void tsplit(const float* __restrict__ in, __nv_bfloat16* __restrict__ oh,
                       __nv_bfloat16* __restrict__ ol, int R, int C) {
    __shared__ float t[32][33];
    size_t base = (size_t)blockIdx.z * R * C;
    int r0 = blockIdx.y * 32, c0 = blockIdx.x * 32;
    int tx = threadIdx.x, ty = threadIdx.y;
#pragma unroll
    for (int i = 0; i < 4; i++)
        t[ty + 8 * i][tx] = in[base + (size_t)(r0 + ty + 8 * i) * C + c0 + tx];
    __syncthreads();
#pragma unroll
    for (int i = 0; i < 4; i++) {
        float v = t[tx][ty + 8 * i];
        __nv_bfloat16 h = __float2bfloat16(v);
        size_t o = base + (size_t)(c0 + ty + 8 * i) * R + r0 + tx;
        oh[o] = h;
        ol[o] = __float2bfloat16(v - __bfloat162float(h));
    }
}

// ---------------- zero bookkeeping ----------------
__global__ void zero_kernel() {
    int i = threadIdx.x;
    if (i < NEXP) { g_counts[i] = 0; g_listcnt[i] = 0; g_psum[i] = 0.0f; }
}

// ---------------- exact fp32 router GEMM ----------------
#define RTM 64
#define RTK 16
__global__ void router_sgemm(const float* __restrict__ A, const float* __restrict__ B,
                             float* __restrict__ Cc)
{
    __shared__ float As[RTK][RTM + 4];
    __shared__ float Bs[RTK][64];
    int tid = threadIdx.x;
    int tx = tid & 15, ty = tid >> 4;
    int bm = blockIdx.y * RTM;
    int la_m = tid >> 2, la_k = (tid & 3) * 4;
    int lb_k = tid >> 4, lb_n = (tid & 15) * 4;
    float acc[4][4];
#pragma unroll
    for (int i = 0; i < 4; i++)
#pragma unroll
        for (int j = 0; j < 4; j++) acc[i][j] = 0.0f;
    for (int k0 = 0; k0 < HID; k0 += RTK) {
        float4 av = *reinterpret_cast<const float4*>(A + (size_t)(bm + la_m) * HID + k0 + la_k);
        As[la_k + 0][la_m] = av.x; As[la_k + 1][la_m] = av.y;
        As[la_k + 2][la_m] = av.z; As[la_k + 3][la_m] = av.w;
        float4 bv = *reinterpret_cast<const float4*>(B + (size_t)(k0 + lb_k) * NEXP + lb_n);
        Bs[lb_k][lb_n + 0] = bv.x; Bs[lb_k][lb_n + 1] = bv.y;
        Bs[lb_k][lb_n + 2] = bv.z; Bs[lb_k][lb_n + 3] = bv.w;
        __syncthreads();
#pragma unroll
        for (int kk = 0; kk < RTK; kk++) {
            float a[4], b[4];
#pragma unroll
            for (int i = 0; i < 4; i++) a[i] = As[kk][ty * 4 + i];
#pragma unroll
            for (int j = 0; j < 4; j++) b[j] = Bs[kk][tx * 4 + j];
#pragma unroll
            for (int i = 0; i < 4; i++)
#pragma unroll
                for (int j = 0; j < 4; j++) acc[i][j] += a[i] * b[j];
        }
        __syncthreads();
    }
#pragma unroll
    for (int i = 0; i < 4; i++)
#pragma unroll
        for (int j = 0; j < 4; j++)
            Cc[(size_t)(bm + ty * 4 + i) * NEXP + tx * 4 + j] = acc[i][j];
}

// ---------------- router top-k / softmax / counts ----------------
__global__ void topk_kernel() {
    int warp = threadIdx.x >> 5, lane = threadIdx.x & 31;
    int t = blockIdx.x * 4 + warp;
    if (t >= T_TOK) return;
    float s0 = g_logits[t * NEXP + lane];
    float s1 = g_logits[t * NEXP + 32 + lane];
    float m = fmaxf(s0, s1);
#pragma unroll
    for (int o = 16; o; o >>= 1) m = fmaxf(m, __shfl_xor_sync(0xffffffffu, m, o));
    float e0 = expf(s0 - m), e1 = expf(s1 - m);
    float d = e0 + e1;
#pragma unroll
    for (int o = 16; o; o >>= 1) d += __shfl_xor_sync(0xffffffffu, d, o);
    float p0 = e0 / d, p1 = e1 / d;

    float mx = fmaxf(p0, p1);
#pragma unroll
    for (int o = 16; o; o >>= 1) mx = fmaxf(mx, __shfl_xor_sync(0xffffffffu, mx, o));
    int cand = 0x7fffffff;
    if (p0 == mx) cand = lane;
    if (p1 == mx) cand = min(cand, lane + 32);
#pragma unroll
    for (int o = 16; o; o >>= 1) cand = min(cand, __shfl_xor_sync(0xffffffffu, cand, o));
    int i1 = cand; float v1 = mx;

    float q0 = (lane == i1) ? -1e30f : p0;
    float q1 = (lane + 32 == i1) ? -1e30f : p1;
    float mx2 = fmaxf(q0, q1);
#pragma unroll
    for (int o = 16; o; o >>= 1) mx2 = fmaxf(mx2, __shfl_xor_sync(0xffffffffu, mx2, o));
    int cand2 = 0x7fffffff;
    if (q0 == mx2) cand2 = lane;
    if (q1 == mx2) cand2 = min(cand2, lane + 32);
#pragma unroll
    for (int o = 16; o; o >>= 1) cand2 = min(cand2, __shfl_xor_sync(0xffffffffu, cand2, o));
    int i2 = cand2; float v2 = mx2;

    if (lane == 0) {
        g_topi[t * 2 + 0] = i1; g_topv[t * 2 + 0] = v1;
        g_topi[t * 2 + 1] = i2; g_topv[t * 2 + 1] = v2;
        atomicAdd(&g_counts[i1], 1);
        atomicAdd(&g_counts[i2], 1);
    }
    atomicAdd(&g_psum[lane], p0);
    atomicAdd(&g_psum[lane + 32], p1);
}

// ---------------- build per-expert slot lists ----------------
__global__ void build_kernel() {
    int a = blockIdx.x * blockDim.x + threadIdx.x;
    if (a >= NASSIGN) return;
    int e = g_topi[a];
    int pos = atomicAdd(&g_listcnt[e], 1);
    if (pos < CAP) {
        g_assign[e * CAP + pos] = a;
        g_slot[a] = pos;
    } else {
        g_slot[a] = -1;
    }
}

// ---------------- split-bf16 mma.sync GEMM ----------------
// C[M,N] = (Ahi+Alo)[M,K] @ (Bhi+Blo)'[N,K]^T, 3-pass: AhBh + AhBl + AlBh.
// CTA 128x128, K-chunk 32, cp.async double buffer, 8 warps (warp tile 64x32).
template<bool GELU_SPLIT, bool GATHER, bool EXPERT>
__global__ void __launch_bounds__(256, 1)
mma_gemm(const __nv_bfloat16* __restrict__ Ahi, const __nv_bfloat16* __restrict__ Alo,
         int lda, long aBatch,
         const __nv_bfloat16* __restrict__ Bhi, const __nv_bfloat16* __restrict__ Blo,
         long bBatch,
         float* __restrict__ outF, __nv_bfloat16* __restrict__ outHi,
         __nv_bfloat16* __restrict__ outLo, int ldc, long cBatch,
         int M, int Kd)
{
    extern __shared__ char smem[];
    const int tid = threadIdx.x;
    const int lane = tid & 31, warp = tid >> 5;
    const int wm = warp & 1, wn = warp >> 1;
    const int bm = blockIdx.y * 128, bn = blockIdx.x * 128;

    int e = 0, cnt = M;
    if (EXPERT) {
        e = blockIdx.z;
        cnt = min(g_listcnt[e], CAP);
        if (bm >= cnt) return;
        if (!GATHER) { Ahi += (size_t)e * aBatch; Alo += (size_t)e * aBatch; }
        Bhi += (size_t)e * bBatch; Blo += (size_t)e * bBatch;
        if (GELU_SPLIT) { outHi += (size_t)e * cBatch; outLo += (size_t)e * cBatch; }
        else            { outF  += (size_t)e * cBatch; }
    }

    int* rowsrc = (int*)(smem + 65536);
    if (GATHER) {
        if (tid < 128) {
            int idx = min(bm + tid, cnt - 1);
            rowsrc[tid] = g_assign[e * CAP + idx] >> 1;   // token index (KTOP=2)
        }
        __syncthreads();
    }
    uint32_t sb = smem_u32(smem);

    const int NC = Kd >> 5;

#define ISSUE_CHUNK(cc, ss) do {                                            \
    int k0_ = (cc) * 32;                                                    \
    uint32_t stb_ = sb + (ss) * 32768;                                      \
    for (int p = tid; p < 512; p += 256) {                                  \
        int r_ = p >> 2, q_ = p & 3;                                        \
        uint32_t so_ = SWZ((uint32_t)(r_ * 64 + q_ * 16));                  \
        size_t ra_ = GATHER ? (size_t)rowsrc[r_] : (size_t)(bm + r_);       \
        size_t ga_ = ra_ * lda + k0_ + q_ * 8;                              \
        cp16(stb_ + so_,         Ahi + ga_);                                \
        cp16(stb_ + 8192 + so_,  Alo + ga_);                                \
        size_t gb_ = (size_t)(bn + r_) * Kd + k0_ + q_ * 8;                 \
        cp16(stb_ + 16384 + so_, Bhi + gb_);                                \
        cp16(stb_ + 24576 + so_, Blo + gb_);                                \
    } } while (0)

    ISSUE_CHUNK(0, 0); CP_COMMIT();
    ISSUE_CHUNK(1, 1); CP_COMMIT();

    float acc[4][4][4];
#pragma unroll
    for (int a = 0; a < 4; a++)
#pragma unroll
        for (int b = 0; b < 4; b++)
#pragma unroll
            for (int c = 0; c < 4; c++) acc[a][b][c] = 0.0f;

    for (int c = 0; c < NC; ++c) {
        CP_WAIT1();
        __syncthreads();
        uint32_t stb = sb + (c & 1) * 32768;
        const int arow = wm * 64 + (lane & 15);
        const int brow = wn * 32 + ((lane >> 4) & 1) * 8 + (lane & 7);
#pragma unroll
        for (int kk = 0; kk < 2; kk++) {
            uint32_t ah[4][4], al[4][4], bh[4][2], bl[4][2];
            uint32_t acol = kk * 32 + ((lane >> 4) << 4);
            uint32_t bcol = kk * 32 + (((lane >> 3) & 1) << 4);
#pragma unroll
            for (int mt = 0; mt < 4; mt++) {
                uint32_t off = SWZ((uint32_t)((arow + mt * 16) * 64) + acol);
                ldm_x4(stb + off, ah[mt][0], ah[mt][1], ah[mt][2], ah[mt][3]);
                ldm_x4(stb + 8192 + off, al[mt][0], al[mt][1], al[mt][2], al[mt][3]);
            }
#pragma unroll
            for (int np = 0; np < 2; np++) {
                uint32_t off = SWZ((uint32_t)((brow + np * 16) * 64) + bcol);
                ldm_x4(stb + 16384 + off, bh[2 * np][0], bh[2 * np][1],
                       bh[2 * np + 1][0], bh[2 * np + 1][1]);
                ldm_x4(stb + 24576 + off, bl[2 * np][0], bl[2 * np][1],
                       bl[2 * np + 1][0], bl[2 * np + 1][1]);
            }
#pragma unroll
            for (int mt = 0; mt < 4; mt++)
#pragma unroll
                for (int nt = 0; nt < 4; nt++) mma_bf16(acc[mt][nt], ah[mt], bh[nt]);
#pragma unroll
            for (int mt = 0; mt < 4; mt++)
#pragma unroll
                for (int nt = 0; nt < 4; nt++) mma_bf16(acc[mt][nt], ah[mt], bl[nt]);
#pragma unroll
            for (int mt = 0; mt < 4; mt++)
#pragma unroll
                for (int nt = 0; nt < 4; nt++) mma_bf16(acc[mt][nt], al[mt], bh[nt]);
        }
        __syncthreads();
        if (c + 2 < NC) ISSUE_CHUNK(c + 2, c & 1);
        CP_COMMIT();
    }
#undef ISSUE_CHUNK

    // epilogue
    const int gr = lane >> 2, gc = (lane & 3) * 2;
#pragma unroll
    for (int mt = 0; mt < 4; mt++) {
#pragma unroll
        for (int nt = 0; nt < 4; nt++) {
            int r0 = bm + wm * 64 + mt * 16 + gr;
            int col = bn + wn * 32 + nt * 8 + gc;
            if (GELU_SPLIT) {
#pragma unroll
                for (int h = 0; h < 2; h++) {
                    int r = r0 + h * 8;
                    if (r < cnt) {
                        float v0 = gelu_f(acc[mt][nt][2 * h]);
                        float v1 = gelu_f(acc[mt][nt][2 * h + 1]);
                        __nv_bfloat16 h0 = __float2bfloat16(v0);
                        __nv_bfloat16 h1 = __float2bfloat16(v1);
                        __nv_bfloat162 hv; hv.x = h0; hv.y = h1;
                        __nv_bfloat162 lv;
                        lv.x = __float2bfloat16(v0 - __bfloat162float(h0));
                        lv.y = __float2bfloat16(v1 - __bfloat162float(h1));
                        *reinterpret_cast<__nv_bfloat162*>(outHi + (size_t)r * ldc + col) = hv;
                        *reinterpret_cast<__nv_bfloat162*>(outLo + (size_t)r * ldc + col) = lv;
                    }
                }
            } else {
#pragma unroll
                for (int h = 0; h < 2; h++) {
                    int r = r0 + h * 8;
                    if (r < cnt) {
                        float2 f2 = make_float2(acc[mt][nt][2 * h], acc[mt][nt][2 * h + 1]);
                        *reinterpret_cast<float2*>(outF + (size_t)r * ldc + col) = f2;
                    }
                }
            }
        }
    }
}

// ---------------- combine ----------------
__global__ void combine_kernel(float* __restrict__ out)
{
    int t = blockIdx.x;
    int a0 = t * 2, a1 = a0 + 1;
    int e0 = g_topi[a0], e1 = g_topi[a1];
    float p0 = g_topv[a0], p1 = g_topv[a1];
    int j0 = g_slot[a0], j1 = g_slot[a1];
    const float* r0 = g_eout + ((size_t)e0 * CAP + (j0 < 0 ? 0 : j0)) * HID;
    const float* r1 = g_eout + ((size_t)e1 * CAP + (j1 < 0 ? 0 : j1)) * HID;
    for (int h = threadIdx.x; h < HID; h += blockDim.x) {
        float v = out[(size_t)t * HID + h];
        if (j0 >= 0) v += p0 * r0[h];
        if (j1 >= 0) v += p1 * r1[h];
        out[(size_t)t * HID + h] = v;
    }
}

// ---------------- aux loss ----------------
__global__ void aux_kernel(float* __restrict__ out, int out_size)
{
    __shared__ float vals[NEXP];
    int i = threadIdx.x;
    if (i < NEXP) {
        float f = (float)g_counts[i] / (float)(T_TOK * KTOP);
        float P = g_psum[i] / (float)T_TOK;
        vals[i] = f * P;
    }
    __syncthreads();
    if (i == 0) {
        float s = 0.0f;
        for (int j = 0; j < NEXP; j++) s += vals[j];
        if (out_size > T_TOK * HID) out[T_TOK * HID] = 0.01f * (float)NEXP * s;
    }
}

// ---------------- launch ----------------
extern "C" void kernel_launch(void* const* d_in, const int* in_sizes, int n_in,
                              void* d_out, int out_size)
{
    const float* x        = (const float*)d_in[0];  // [T,H]
    const float* w_router = (const float*)d_in[1];  // [H,E]
    const float* w1       = (const float*)d_in[2];  // [E,H,F]
    const float* w2       = (const float*)d_in[3];  // [E,F,H]
    const float* ws1      = (const float*)d_in[4];  // [H,SF]
    const float* ws2      = (const float*)d_in[5];  // [SF,H]
    float* out = (float*)d_out;

    float* logits; cudaGetSymbolAddress((void**)&logits, g_logits);
    __nv_bfloat16 *xhi, *xlo, *w1th, *w1tl, *w2th, *w2tl, *ws1th, *ws1tl, *ws2th, *ws2tl;
    __nv_bfloat16 *hh, *hl, *sh, *sl;
    float* eout;
    cudaGetSymbolAddress((void**)&xhi,  g_xhi);   cudaGetSymbolAddress((void**)&xlo,  g_xlo);
    cudaGetSymbolAddress((void**)&w1th, g_w1th);  cudaGetSymbolAddress((void**)&w1tl, g_w1tl);
    cudaGetSymbolAddress((void**)&w2th, g_w2th);  cudaGetSymbolAddress((void**)&w2tl, g_w2tl);
    cudaGetSymbolAddress((void**)&ws1th, g_ws1th); cudaGetSymbolAddress((void**)&ws1tl, g_ws1tl);
    cudaGetSymbolAddress((void**)&ws2th, g_ws2th); cudaGetSymbolAddress((void**)&ws2tl, g_ws2tl);
    cudaGetSymbolAddress((void**)&hh, g_hh);      cudaGetSymbolAddress((void**)&hl, g_hl);
    cudaGetSymbolAddress((void**)&sh, g_sh);      cudaGetSymbolAddress((void**)&sl, g_sl);
    cudaGetSymbolAddress((void**)&eout, g_eout);

    const int SMB = 65536 + 512;
    cudaFuncSetAttribute(mma_gemm<true,  true,  true >, cudaFuncAttributeMaxDynamicSharedMemorySize, SMB);
    cudaFuncSetAttribute(mma_gemm<false, false, true >, cudaFuncAttributeMaxDynamicSharedMemorySize, SMB);
    cudaFuncSetAttribute(mma_gemm<true,  false, false>, cudaFuncAttributeMaxDynamicSharedMemorySize, SMB);
    cudaFuncSetAttribute(mma_gemm<false, false, false>, cudaFuncAttributeMaxDynamicSharedMemorySize, SMB);

    // ---- prepasses: split x; transpose+split all weight matrices ----
    csplit<<<4096, 256>>>(x, xhi, xlo, T_TOK * HID);
    tsplit<<<dim3(FFN / 32, HID / 32, NEXP), dim3(32, 8)>>>(w1, w1th, w1tl, HID, FFN);
    tsplit<<<dim3(HID / 32, FFN / 32, NEXP), dim3(32, 8)>>>(w2, w2th, w2tl, FFN, HID);
    tsplit<<<dim3(SFFN / 32, HID / 32, 1), dim3(32, 8)>>>(ws1, ws1th, ws1tl, HID, SFFN);
    tsplit<<<dim3(HID / 32, SFFN / 32, 1), dim3(32, 8)>>>(ws2, ws2th, ws2tl, SFFN, HID);

    zero_kernel<<<1, 256>>>();

    // ---- router (exact fp32) + routing ----
    router_sgemm<<<dim3(1, T_TOK / RTM), 256>>>(x, w_router, logits);
    topk_kernel<<<T_TOK / 4, 128>>>();
    build_kernel<<<(NASSIGN + 255) / 256, 256>>>();

    // ---- expert MLP (mma.sync split-bf16) ----
    mma_gemm<true, true, true><<<dim3(FFN / 128, CAP / 128, NEXP), 256, SMB>>>(
        xhi, xlo, HID, 0,
        w1th, w1tl, (long)FFN * HID,
        nullptr, hh, hl, FFN, (long)CAP * FFN,
        CAP, HID);
    mma_gemm<false, false, true><<<dim3(HID / 128, CAP / 128, NEXP), 256, SMB>>>(
        hh, hl, FFN, (long)CAP * FFN,
        w2th, w2tl, (long)HID * FFN,
        eout, nullptr, nullptr, HID, (long)CAP * HID,
        CAP, FFN);

    // ---- shared expert ----
    mma_gemm<true, false, false><<<dim3(SFFN / 128, T_TOK / 128, 1), 256, SMB>>>(
        xhi, xlo, HID, 0,
        ws1th, ws1tl, 0,
        nullptr, sh, sl, SFFN, 0,
        T_TOK, HID);
    mma_gemm<false, false, false><<<dim3(HID / 128, T_TOK / 128, 1), 256, SMB>>>(
        sh, sl, SFFN, 0,
        ws2th, ws2tl, 0,
        out, nullptr, nullptr, HID, 0,
        T_TOK, SFFN);

    // ---- combine + aux ----
    combine_kernel<<<T_TOK, 256>>>(out);
    aux_kernel<<<1, 64>>>(out, out_size);
}

// round 5
// speedup vs baseline: 5.0842x; 1.5122x over previous
#include <cuda_runtime.h>
#include <cuda_fp16.h>
#include <math.h>
#include <stdint.h>

// ---------------- problem constants ----------------
#define T_TOK 8192
#define HID   1024
#define NEXP  64
#define KTOP  2
#define CAP   1024
#define FFN   512
#define SFFN  1024
#define NASSIGN (T_TOK*KTOP)

// ---------------- helpers (compute_103-safe PTX only) ----------------
__device__ __forceinline__ uint32_t smem_u32(const void* p) {
    uint32_t a;
    asm("{ .reg .u64 t; cvta.to.shared.u64 t, %1; cvt.u32.u64 %0, t; }" : "=r"(a) : "l"(p));
    return a;
}
__device__ __forceinline__ void ldm_x4(uint32_t addr, uint32_t& r0, uint32_t& r1,
                                       uint32_t& r2, uint32_t& r3) {
    asm volatile("ldmatrix.sync.aligned.m8n8.x4.shared.b16 {%0,%1,%2,%3}, [%4];"
        : "=r"(r0), "=r"(r1), "=r"(r2), "=r"(r3) : "r"(addr));
}
__device__ __forceinline__ void ldm_x4t(uint32_t addr, uint32_t& r0, uint32_t& r1,
                                        uint32_t& r2, uint32_t& r3) {
    asm volatile("ldmatrix.sync.aligned.m8n8.x4.trans.shared.b16 {%0,%1,%2,%3}, [%4];"
        : "=r"(r0), "=r"(r1), "=r"(r2), "=r"(r3) : "r"(addr));
}
__device__ __forceinline__ void mma_fp16(float* d, const uint32_t* a, uint32_t b0, uint32_t b1) {
    asm volatile("mma.sync.aligned.m16n8k16.row.col.f32.f16.f16.f32 "
        "{%0,%1,%2,%3}, {%4,%5,%6,%7}, {%8,%9}, {%0,%1,%2,%3};"
        : "+f"(d[0]), "+f"(d[1]), "+f"(d[2]), "+f"(d[3])
        : "r"(a[0]), "r"(a[1]), "r"(a[2]), "r"(a[3]), "r"(b0), "r"(b1));
}
__device__ __forceinline__ void cp16(uint32_t dst, const void* src) {
    size_t g = __cvta_generic_to_global(src);
    asm volatile("cp.async.cg.shared.global [%0], [%1], 16;" :: "r"(dst), "l"(g));
}
#define CP_COMMIT() asm volatile("cp.async.commit_group;" ::: "memory")
#define CP_WAIT1()  asm volatile("cp.async.wait_group 1;" ::: "memory")
// A tiles: 128B rows -> SW128 (chunk[4:6] ^= row&7)
#define SWA(o) ((o) ^ (((o) >> 3) & 0x70))
// B tiles: 256B rows -> chunk[4:6] ^= k&7
#define SWB(o) ((o) ^ (((o) >> 4) & 0x70))

// ---------------- scratch (device globals; allocation is forbidden) ----------
__device__ float g_logits[T_TOK * NEXP];
__device__ int   g_topi[NASSIGN];
__device__ float g_topv[NASSIGN];
__device__ int   g_counts[NEXP];
__device__ int   g_listcnt[NEXP];
__device__ float g_psum[NEXP];
__device__ int   g_assign[NEXP * CAP];

__device__ __align__(16) __half g_xh[T_TOK * HID];                  // 16 MB
__device__ __align__(16) __half g_w1h[(size_t)NEXP * HID * FFN];    // 64 MB
__device__ __align__(16) __half g_w1l[(size_t)NEXP * HID * FFN];
__device__ __align__(16) __half g_w2h[(size_t)NEXP * FFN * HID];
__device__ __align__(16) __half g_w2l[(size_t)NEXP * FFN * HID];
__device__ __align__(16) __half g_ws1h[(size_t)HID * SFFN];
__device__ __align__(16) __half g_ws1l[(size_t)HID * SFFN];
__device__ __align__(16) __half g_ws2h[(size_t)SFFN * HID];
__device__ __align__(16) __half g_ws2l[(size_t)SFFN * HID];
__device__ __align__(16) __half g_h[(size_t)NEXP * CAP * FFN];      // 64 MB
__device__ __align__(16) __half g_s[(size_t)T_TOK * SFFN];          // 16 MB

__device__ __forceinline__ float gelu_f(float x) {
    float x3 = x * x * x;
    return 0.5f * x * (1.0f + tanhf(0.7978845608028654f * (x + 0.044715f * x3)));
}

// ---------------- prepass: fp32 -> fp16 (single) ----------------
__global__ void cvt1(const float* __restrict__ in, __half* __restrict__ o, int n) {
    int i = (blockIdx.x * blockDim.x + threadIdx.x) * 4;
    int s = gridDim.x * blockDim.x * 4;
    for (; i < n; i += s) {
        float4 v = *reinterpret_cast<const float4*>(in + i);
        *reinterpret_cast<__half2*>(o + i)     = __floats2half2_rn(v.x, v.y);
        *reinterpret_cast<__half2*>(o + i + 2) = __floats2half2_rn(v.z, v.w);
    }
}
// ---------------- prepass: fp32 -> fp16 hi + fp16 residual ----------------
__global__ void cvt2(const float* __restrict__ in, __half* __restrict__ oh,
                     __half* __restrict__ ol, int n) {
    int i = (blockIdx.x * blockDim.x + threadIdx.x) * 4;
    int s = gridDim.x * blockDim.x * 4;
    for (; i < n; i += s) {
        float4 v = *reinterpret_cast<const float4*>(in + i);
        __half h0 = __float2half(v.x), h1 = __float2half(v.y);
        __half h2 = __float2half(v.z), h3 = __float2half(v.w);
        __half2 a; a.x = h0; a.y = h1;
        __half2 b; b.x = h2; b.y = h3;
        *reinterpret_cast<__half2*>(oh + i)     = a;
        *reinterpret_cast<__half2*>(oh + i + 2) = b;
        __half2 la = __floats2half2_rn(v.x - __half2float(h0), v.y - __half2float(h1));
        __half2 lb = __floats2half2_rn(v.z - __half2float(h2), v.w - __half2float(h3));
        *reinterpret_cast<__half2*>(ol + i)     = la;
        *reinterpret_cast<__half2*>(ol + i + 2) = lb;
    }
}

// ---------------- zero bookkeeping ----------------
__global__ void zero_kernel() {
    int i = threadIdx.x;
    if (i < NEXP) { g_counts[i] = 0; g_listcnt[i] = 0; g_psum[i] = 0.0f; }
}

// ---------------- exact fp32 router GEMM ----------------
#define RTM 64
#define RTK 16
__global__ void router_sgemm(const float* __restrict__ A, const float* __restrict__ B,
                             float* __restrict__ Cc)
{
    __shared__ float As[RTK][RTM + 4];
    __shared__ float Bs[RTK][64];
    int tid = threadIdx.x;
    int tx = tid & 15, ty = tid >> 4;
    int bm = blockIdx.y * RTM;
    int la_m = tid >> 2, la_k = (tid & 3) * 4;
    int lb_k = tid >> 4, lb_n = (tid & 15) * 4;
    float acc[4][4];
#pragma unroll
    for (int i = 0; i < 4; i++)
#pragma unroll
        for (int j = 0; j < 4; j++) acc[i][j] = 0.0f;
    for (int k0 = 0; k0 < HID; k0 += RTK) {
        float4 av = *reinterpret_cast<const float4*>(A + (size_t)(bm + la_m) * HID + k0 + la_k);
        As[la_k + 0][la_m] = av.x; As[la_k + 1][la_m] = av.y;
        As[la_k + 2][la_m] = av.z; As[la_k + 3][la_m] = av.w;
        float4 bv = *reinterpret_cast<const float4*>(B + (size_t)(k0 + lb_k) * NEXP + lb_n);
        Bs[lb_k][lb_n + 0] = bv.x; Bs[lb_k][lb_n + 1] = bv.y;
        Bs[lb_k][lb_n + 2] = bv.z; Bs[lb_k][lb_n + 3] = bv.w;
        __syncthreads();
#pragma unroll
        for (int kk = 0; kk < RTK; kk++) {
            float a[4], b[4];
#pragma unroll
            for (int i = 0; i < 4; i++) a[i] = As[kk][ty * 4 + i];
#pragma unroll
            for (int j = 0; j < 4; j++) b[j] = Bs[kk][tx * 4 + j];
#pragma unroll
            for (int i = 0; i < 4; i++)
#pragma unroll
                for (int j = 0; j < 4; j++) acc[i][j] += a[i] * b[j];
        }
        __syncthreads();
    }
#pragma unroll
    for (int i = 0; i < 4; i++)
#pragma unroll
        for (int j = 0; j < 4; j++)
            Cc[(size_t)(bm + ty * 4 + i) * NEXP + tx * 4 + j] = acc[i][j];
}

// ---------------- router top-k / softmax / counts ----------------
__global__ void topk_kernel() {
    int warp = threadIdx.x >> 5, lane = threadIdx.x & 31;
    int t = blockIdx.x * 4 + warp;
    if (t >= T_TOK) return;
    float s0 = g_logits[t * NEXP + lane];
    float s1 = g_logits[t * NEXP + 32 + lane];
    float m = fmaxf(s0, s1);
#pragma unroll
    for (int o = 16; o; o >>= 1) m = fmaxf(m, __shfl_xor_sync(0xffffffffu, m, o));
    float e0 = expf(s0 - m), e1 = expf(s1 - m);
    float d = e0 + e1;
#pragma unroll
    for (int o = 16; o; o >>= 1) d += __shfl_xor_sync(0xffffffffu, d, o);
    float p0 = e0 / d, p1 = e1 / d;

    float mx = fmaxf(p0, p1);
#pragma unroll
    for (int o = 16; o; o >>= 1) mx = fmaxf(mx, __shfl_xor_sync(0xffffffffu, mx, o));
    int cand = 0x7fffffff;
    if (p0 == mx) cand = lane;
    if (p1 == mx) cand = min(cand, lane + 32);
#pragma unroll
    for (int o = 16; o; o >>= 1) cand = min(cand, __shfl_xor_sync(0xffffffffu, cand, o));
    int i1 = cand; float v1 = mx;

    float q0 = (lane == i1) ? -1e30f : p0;
    float q1 = (lane + 32 == i1) ? -1e30f : p1;
    float mx2 = fmaxf(q0, q1);
#pragma unroll
    for (int o = 16; o; o >>= 1) mx2 = fmaxf(mx2, __shfl_xor_sync(0xffffffffu, mx2, o));
    int cand2 = 0x7fffffff;
    if (q0 == mx2) cand2 = lane;
    if (q1 == mx2) cand2 = min(cand2, lane + 32);
#pragma unroll
    for (int o = 16; o; o >>= 1) cand2 = min(cand2, __shfl_xor_sync(0xffffffffu, cand2, o));
    int i2 = cand2; float v2 = mx2;

    if (lane == 0) {
        g_topi[t * 2 + 0] = i1; g_topv[t * 2 + 0] = v1;
        g_topi[t * 2 + 1] = i2; g_topv[t * 2 + 1] = v2;
        atomicAdd(&g_counts[i1], 1);
        atomicAdd(&g_counts[i2], 1);
    }
    atomicAdd(&g_psum[lane], p0);
    atomicAdd(&g_psum[lane + 32], p1);
}

// ---------------- build per-expert slot lists ----------------
__global__ void build_kernel() {
    int a = blockIdx.x * blockDim.x + threadIdx.x;
    if (a >= NASSIGN) return;
    int e = g_topi[a];
    int pos = atomicAdd(&g_listcnt[e], 1);
    if (pos < CAP) g_assign[e * CAP + pos] = a;
}

// ---------------- fp16 2-pass mma.sync GEMM ----------------
// C[M,N] = A[M,K] @ (Bh+Bl)[K,N]   (B row-major [K][N], loaded via ldmatrix.trans)
// CTA 128x128, K-chunk 64, double-buffered cp.async, 8 warps (warp tile 64x32).
// EPI: 0 = gelu -> fp16 out, 1 = f32 store, 2 = atomic combine into out[token]
#define STAGE_BYTES 49152   // A 16K + Bh 16K + Bl 16K
#define MISC_OFF    98304   // 2 stages

template<int EPI, bool GATHER, bool EXPERT>
__global__ void __launch_bounds__(256, 2)
mma_gemm(const __half* __restrict__ A, int lda, long aBatch,
         const __half* __restrict__ Bh, const __half* __restrict__ Bl,
         int ldb, long bBatch,
         __half* __restrict__ outH, float* __restrict__ outF, int ldc, long cBatch,
         int M, int Kd)
{
    extern __shared__ char smem[];
    const int tid = threadIdx.x;
    const int lane = tid & 31, warp = tid >> 5;
    const int wm = warp & 1, wn = warp >> 1;
    const int bm = blockIdx.y * 128, bn = blockIdx.x * 128;

    int e = 0, cnt = M;
    if (EXPERT) {
        e = blockIdx.z;
        cnt = min(g_listcnt[e], CAP);
        if (bm >= cnt) return;
        if (aBatch) A += (size_t)e * aBatch;
        Bh += (size_t)e * bBatch; Bl += (size_t)e * bBatch;
        if (EPI == 0) outH += (size_t)e * cBatch;
    }

    int*   tok = (int*)(smem + MISC_OFF);
    float* pw  = (float*)(smem + MISC_OFF + 512);
    if ((GATHER || EPI == 2) && tid < 128) {
        int idx = min(bm + tid, cnt - 1);
        int a = g_assign[e * CAP + idx];
        tok[tid] = a >> 1;                    // token (KTOP=2)
        pw[tid]  = g_topv[a];
    }
    __syncthreads();

    uint32_t sb = smem_u32(smem);
    const int NC = Kd >> 6;

#define ISSUE_CHUNK(cc, ss) do {                                              \
    int k0_ = (cc) * 64;                                                      \
    uint32_t st_ = sb + (ss) * STAGE_BYTES;                                   \
    for (int p = tid; p < 1024; p += 256) {       /* A: 128 x 64 fp16 */      \
        int r_ = p >> 3, q_ = p & 7;                                          \
        size_t row_ = GATHER ? (size_t)tok[r_] : (size_t)(bm + r_);           \
        cp16(st_ + SWA((uint32_t)(r_ * 128 + q_ * 16)),                       \
             A + row_ * lda + k0_ + q_ * 8);                                  \
    }                                                                         \
    for (int p = tid; p < 1024; p += 256) {       /* B: 64 x 128 fp16 x2 */   \
        int kr_ = p >> 4, nq_ = p & 15;                                       \
        size_t gb_ = (size_t)(k0_ + kr_) * ldb + bn + nq_ * 8;                \
        uint32_t so_ = SWB((uint32_t)(kr_ * 256 + nq_ * 16));                 \
        cp16(st_ + 16384 + so_, Bh + gb_);                                    \
        cp16(st_ + 32768 + so_, Bl + gb_);                                    \
    } } while (0)

    ISSUE_CHUNK(0, 0); CP_COMMIT();
    ISSUE_CHUNK(1, 1); CP_COMMIT();

    float acc[4][4][4];
#pragma unroll
    for (int a = 0; a < 4; a++)
#pragma unroll
        for (int b = 0; b < 4; b++)
#pragma unroll
            for (int c = 0; c < 4; c++) acc[a][b][c] = 0.0f;

    for (int c = 0; c < NC; ++c) {
        CP_WAIT1();
        __syncthreads();
        uint32_t sA  = sb + (c & 1) * STAGE_BYTES;
        uint32_t sBh = sA + 16384;
        uint32_t sBl = sA + 32768;
#pragma unroll
        for (int kk = 0; kk < 4; kk++) {
            uint32_t af[4][4];
#pragma unroll
            for (int mt = 0; mt < 4; mt++) {
                uint32_t off = SWA((uint32_t)((wm * 64 + mt * 16 + (lane & 15)) * 128
                                              + kk * 32 + ((lane >> 4) << 4)));
                ldm_x4(sA + off, af[mt][0], af[mt][1], af[mt][2], af[mt][3]);
            }
#pragma unroll
            for (int ntp = 0; ntp < 2; ntp++) {
                uint32_t boff = SWB((uint32_t)((kk * 16 + (lane & 15)) * 256
                                + (wn * 32 + ntp * 16 + ((lane >> 4) << 3)) * 2));
                uint32_t b0, b1, b2, b3;
                ldm_x4t(sBh + boff, b0, b1, b2, b3);
#pragma unroll
                for (int mt = 0; mt < 4; mt++) {
                    mma_fp16(acc[mt][ntp * 2],     af[mt], b0, b1);
                    mma_fp16(acc[mt][ntp * 2 + 1], af[mt], b2, b3);
                }
                ldm_x4t(sBl + boff, b0, b1, b2, b3);
#pragma unroll
                for (int mt = 0; mt < 4; mt++) {
                    mma_fp16(acc[mt][ntp * 2],     af[mt], b0, b1);
                    mma_fp16(acc[mt][ntp * 2 + 1], af[mt], b2, b3);
                }
            }
        }
        __syncthreads();
        if (c + 2 < NC) ISSUE_CHUNK(c + 2, c & 1);
        CP_COMMIT();
    }
#undef ISSUE_CHUNK

    const int gr = lane >> 2, gc = (lane & 3) * 2;
    if (EPI == 2) {
        // stage tile in smem, then coalesced atomic combine
        float* tile = (float*)smem;   // 128x128 f32 = 64KB (stages are dead now)
#pragma unroll
        for (int mt = 0; mt < 4; mt++)
#pragma unroll
            for (int nt = 0; nt < 4; nt++)
#pragma unroll
                for (int h = 0; h < 2; h++) {
                    int rl = wm * 64 + mt * 16 + gr + h * 8;
                    int cl = wn * 32 + nt * 8 + gc;
                    *reinterpret_cast<float2*>(&tile[rl * 128 + cl]) =
                        make_float2(acc[mt][nt][2 * h], acc[mt][nt][2 * h + 1]);
                }
        __syncthreads();
        for (int r = warp; r < 128; r += 8) {
            if (bm + r < cnt) {
                float p = pw[r];
                float* base = outF + (size_t)tok[r] * HID + bn;
                for (int cc = lane; cc < 128; cc += 32)
                    atomicAdd(base + cc, p * tile[r * 128 + cc]);
            }
        }
    } else {
#pragma unroll
        for (int mt = 0; mt < 4; mt++)
#pragma unroll
            for (int nt = 0; nt < 4; nt++)
#pragma unroll
                for (int h = 0; h < 2; h++) {
                    int r = bm + wm * 64 + mt * 16 + gr + h * 8;
                    if (r >= cnt) continue;
                    int col = bn + wn * 32 + nt * 8 + gc;
                    if (EPI == 0) {
                        __half2 hv = __floats2half2_rn(gelu_f(acc[mt][nt][2 * h]),
                                                       gelu_f(acc[mt][nt][2 * h + 1]));
                        *reinterpret_cast<__half2*>(outH + (size_t)r * ldc + col) = hv;
                    } else {
                        *reinterpret_cast<float2*>(outF + (size_t)r * ldc + col) =
                            make_float2(acc[mt][nt][2 * h], acc[mt][nt][2 * h + 1]);
                    }
                }
    }
}

// ---------------- aux loss ----------------
__global__ void aux_kernel(float* __restrict__ out, int out_size)
{
    __shared__ float vals[NEXP];
    int i = threadIdx.x;
    if (i < NEXP) {
        float f = (float)g_counts[i] / (float)(T_TOK * KTOP);
        float P = g_psum[i] / (float)T_TOK;
        vals[i] = f * P;
    }
    __syncthreads();
    if (i == 0) {
        float s = 0.0f;
        for (int j = 0; j < NEXP; j++) s += vals[j];
        if (out_size > T_TOK * HID) out[T_TOK * HID] = 0.01f * (float)NEXP * s;
    }
}

// ---------------- launch ----------------
extern "C" void kernel_launch(void* const* d_in, const int* in_sizes, int n_in,
                              void* d_out, int out_size)
{
    const float* x        = (const float*)d_in[0];  // [T,H]
    const float* w_router = (const float*)d_in[1];  // [H,E]
    const float* w1       = (const float*)d_in[2];  // [E,H,F]
    const float* w2       = (const float*)d_in[3];  // [E,F,H]
    const float* ws1      = (const float*)d_in[4];  // [H,SF]
    const float* ws2      = (const float*)d_in[5];  // [SF,H]
    float* out = (float*)d_out;

    float* logits; cudaGetSymbolAddress((void**)&logits, g_logits);
    __half *xh, *w1h, *w1l, *w2h, *w2l, *ws1h, *ws1l, *ws2h, *ws2l, *hbuf, *sbuf;
    cudaGetSymbolAddress((void**)&xh,  g_xh);
    cudaGetSymbolAddress((void**)&w1h, g_w1h);   cudaGetSymbolAddress((void**)&w1l, g_w1l);
    cudaGetSymbolAddress((void**)&w2h, g_w2h);   cudaGetSymbolAddress((void**)&w2l, g_w2l);
    cudaGetSymbolAddress((void**)&ws1h, g_ws1h); cudaGetSymbolAddress((void**)&ws1l, g_ws1l);
    cudaGetSymbolAddress((void**)&ws2h, g_ws2h); cudaGetSymbolAddress((void**)&ws2l, g_ws2l);
    cudaGetSymbolAddress((void**)&hbuf, g_h);    cudaGetSymbolAddress((void**)&sbuf, g_s);

    const int SMB = MISC_OFF + 1024;   // 2 stages + tok/pw
    cudaFuncSetAttribute(mma_gemm<0, true,  true >, cudaFuncAttributeMaxDynamicSharedMemorySize, SMB);
    cudaFuncSetAttribute(mma_gemm<2, false, true >, cudaFuncAttributeMaxDynamicSharedMemorySize, SMB);
    cudaFuncSetAttribute(mma_gemm<0, false, false>, cudaFuncAttributeMaxDynamicSharedMemorySize, SMB);
    cudaFuncSetAttribute(mma_gemm<1, false, false>, cudaFuncAttributeMaxDynamicSharedMemorySize, SMB);

    // ---- prepass conversions (no transposes needed: B consumed K-major) ----
    cvt1<<<1024, 256>>>(x, xh, T_TOK * HID);
    cvt2<<<4096, 256>>>(w1, w1h, w1l, NEXP * HID * FFN);
    cvt2<<<4096, 256>>>(w2, w2h, w2l, NEXP * FFN * HID);
    cvt2<<<512, 256>>>(ws1, ws1h, ws1l, HID * SFFN);
    cvt2<<<512, 256>>>(ws2, ws2h, ws2l, SFFN * HID);

    zero_kernel<<<1, 256>>>();

    // ---- router (exact fp32) + routing ----
    router_sgemm<<<dim3(1, T_TOK / RTM), 256>>>(x, w_router, logits);
    topk_kernel<<<T_TOK / 4, 128>>>();
    build_kernel<<<(NASSIGN + 255) / 256, 256>>>();

    // ---- shared expert (writes base of out) ----
    mma_gemm<0, false, false><<<dim3(SFFN / 128, T_TOK / 128), 256, SMB>>>(
        xh, HID, 0, ws1h, ws1l, SFFN, 0, sbuf, nullptr, SFFN, 0, T_TOK, HID);
    mma_gemm<1, false, false><<<dim3(HID / 128, T_TOK / 128), 256, SMB>>>(
        sbuf, SFFN, 0, ws2h, ws2l, HID, 0, nullptr, out, HID, 0, T_TOK, SFFN);

    // ---- expert MLP; gemm2 atomically combines into out ----
    mma_gemm<0, true, true><<<dim3(FFN / 128, CAP / 128, NEXP), 256, SMB>>>(
        xh, HID, 0, w1h, w1l, FFN, (long)HID * FFN, hbuf, nullptr, FFN, (long)CAP * FFN,
        CAP, HID);
    mma_gemm<2, false, true><<<dim3(HID / 128, CAP / 128, NEXP), 256, SMB>>>(
        hbuf, FFN, (long)CAP * FFN, w2h, w2l, HID, (long)FFN * HID,
        nullptr, out, HID, 0, CAP, FFN);

    aux_kernel<<<1, 64>>>(out, out_size);
}

// round 6
// speedup vs baseline: 6.9803x; 1.3730x over previous
#include <cuda_runtime.h>
#include <cuda_fp16.h>
#include <math.h>
#include <stdint.h>

// ---------------- problem constants ----------------
#define T_TOK 8192
#define HID   1024
#define NEXP  64
#define KTOP  2
#define CAP   1024
#define FFN   512
#define SFFN  1024
#define NASSIGN (T_TOK*KTOP)

// ---------------- helpers (compute_103-safe PTX only) ----------------
__device__ __forceinline__ uint32_t smem_u32(const void* p) {
    uint32_t a;
    asm("{ .reg .u64 t; cvta.to.shared.u64 t, %1; cvt.u32.u64 %0, t; }" : "=r"(a) : "l"(p));
    return a;
}
__device__ __forceinline__ void ldm_x4(uint32_t addr, uint32_t& r0, uint32_t& r1,
                                       uint32_t& r2, uint32_t& r3) {
    asm volatile("ldmatrix.sync.aligned.m8n8.x4.shared.b16 {%0,%1,%2,%3}, [%4];"
        : "=r"(r0), "=r"(r1), "=r"(r2), "=r"(r3) : "r"(addr));
}
__device__ __forceinline__ void ldm_x4t(uint32_t addr, uint32_t& r0, uint32_t& r1,
                                        uint32_t& r2, uint32_t& r3) {
    asm volatile("ldmatrix.sync.aligned.m8n8.x4.trans.shared.b16 {%0,%1,%2,%3}, [%4];"
        : "=r"(r0), "=r"(r1), "=r"(r2), "=r"(r3) : "r"(addr));
}
__device__ __forceinline__ void mma_fp16(float* d, const uint32_t* a, uint32_t b0, uint32_t b1) {
    asm volatile("mma.sync.aligned.m16n8k16.row.col.f32.f16.f16.f32 "
        "{%0,%1,%2,%3}, {%4,%5,%6,%7}, {%8,%9}, {%0,%1,%2,%3};"
        : "+f"(d[0]), "+f"(d[1]), "+f"(d[2]), "+f"(d[3])
        : "r"(a[0]), "r"(a[1]), "r"(a[2]), "r"(a[3]), "r"(b0), "r"(b1));
}
__device__ __forceinline__ void cp16(uint32_t dst, const void* src) {
    size_t g = __cvta_generic_to_global(src);
    asm volatile("cp.async.cg.shared.global [%0], [%1], 16;" :: "r"(dst), "l"(g));
}
#define CP_COMMIT() asm volatile("cp.async.commit_group;" ::: "memory")
#define CP_WAIT1()  asm volatile("cp.async.wait_group 1;" ::: "memory")
// A tiles: 128B rows -> SW128 (chunk[4:6] ^= row&7)
#define SWA(o) ((o) ^ (((o) >> 3) & 0x70))
// B tiles: 256B rows -> chunk[4:6] ^= k&7
#define SWB(o) ((o) ^ (((o) >> 4) & 0x70))

// ---------------- scratch (device globals; allocation is forbidden) ----------
__device__ float g_logits[T_TOK * NEXP];
__device__ int   g_topi[NASSIGN];
__device__ float g_topv[NASSIGN];
__device__ int   g_counts[NEXP];
__device__ int   g_listcnt[NEXP];
__device__ float g_psum[NEXP];
__device__ int   g_assign[NEXP * CAP];

__device__ __align__(16) __half g_xh[T_TOK * HID];                  // 16 MB
__device__ __align__(16) __half g_w1h[(size_t)NEXP * HID * FFN];    // 64 MB
__device__ __align__(16) __half g_w2h[(size_t)NEXP * FFN * HID];    // 64 MB
__device__ __align__(16) __half g_ws1h[(size_t)HID * SFFN];
__device__ __align__(16) __half g_ws2h[(size_t)SFFN * HID];
__device__ __align__(16) __half g_h[(size_t)NEXP * CAP * FFN];      // 64 MB
__device__ __align__(16) __half g_s[(size_t)T_TOK * SFFN];          // 16 MB

__device__ __forceinline__ float gelu_f(float x) {
    float x3 = x * x * x;
    return 0.5f * x * (1.0f + tanhf(0.7978845608028654f * (x + 0.044715f * x3)));
}

// ---------------- prepass: fp32 -> fp16 ----------------
__global__ void cvt1(const float* __restrict__ in, __half* __restrict__ o, int n) {
    int i = (blockIdx.x * blockDim.x + threadIdx.x) * 4;
    int s = gridDim.x * blockDim.x * 4;
    for (; i < n; i += s) {
        float4 v = *reinterpret_cast<const float4*>(in + i);
        *reinterpret_cast<__half2*>(o + i)     = __floats2half2_rn(v.x, v.y);
        *reinterpret_cast<__half2*>(o + i + 2) = __floats2half2_rn(v.z, v.w);
    }
}

// ---------------- zero bookkeeping ----------------
__global__ void zero_kernel() {
    int i = threadIdx.x;
    if (i < NEXP) { g_counts[i] = 0; g_listcnt[i] = 0; g_psum[i] = 0.0f; }
}

// ---------------- exact fp32 router GEMM ----------------
#define RTM 64
#define RTK 16
__global__ void router_sgemm(const float* __restrict__ A, const float* __restrict__ B,
                             float* __restrict__ Cc)
{
    __shared__ float As[RTK][RTM + 4];
    __shared__ float Bs[RTK][64];
    int tid = threadIdx.x;
    int tx = tid & 15, ty = tid >> 4;
    int bm = blockIdx.y * RTM;
    int la_m = tid >> 2, la_k = (tid & 3) * 4;
    int lb_k = tid >> 4, lb_n = (tid & 15) * 4;
    float acc[4][4];
#pragma unroll
    for (int i = 0; i < 4; i++)
#pragma unroll
        for (int j = 0; j < 4; j++) acc[i][j] = 0.0f;
    for (int k0 = 0; k0 < HID; k0 += RTK) {
        float4 av = *reinterpret_cast<const float4*>(A + (size_t)(bm + la_m) * HID + k0 + la_k);
        As[la_k + 0][la_m] = av.x; As[la_k + 1][la_m] = av.y;
        As[la_k + 2][la_m] = av.z; As[la_k + 3][la_m] = av.w;
        float4 bv = *reinterpret_cast<const float4*>(B + (size_t)(k0 + lb_k) * NEXP + lb_n);
        Bs[lb_k][lb_n + 0] = bv.x; Bs[lb_k][lb_n + 1] = bv.y;
        Bs[lb_k][lb_n + 2] = bv.z; Bs[lb_k][lb_n + 3] = bv.w;
        __syncthreads();
#pragma unroll
        for (int kk = 0; kk < RTK; kk++) {
            float a[4], b[4];
#pragma unroll
            for (int i = 0; i < 4; i++) a[i] = As[kk][ty * 4 + i];
#pragma unroll
            for (int j = 0; j < 4; j++) b[j] = Bs[kk][tx * 4 + j];
#pragma unroll
            for (int i = 0; i < 4; i++)
#pragma unroll
                for (int j = 0; j < 4; j++) acc[i][j] += a[i] * b[j];
        }
        __syncthreads();
    }
#pragma unroll
    for (int i = 0; i < 4; i++)
#pragma unroll
        for (int j = 0; j < 4; j++)
            Cc[(size_t)(bm + ty * 4 + i) * NEXP + tx * 4 + j] = acc[i][j];
}

// ---------------- router top-k / softmax / counts ----------------
__global__ void topk_kernel() {
    int warp = threadIdx.x >> 5, lane = threadIdx.x & 31;
    int t = blockIdx.x * 4 + warp;
    if (t >= T_TOK) return;
    float s0 = g_logits[t * NEXP + lane];
    float s1 = g_logits[t * NEXP + 32 + lane];
    float m = fmaxf(s0, s1);
#pragma unroll
    for (int o = 16; o; o >>= 1) m = fmaxf(m, __shfl_xor_sync(0xffffffffu, m, o));
    float e0 = expf(s0 - m), e1 = expf(s1 - m);
    float d = e0 + e1;
#pragma unroll
    for (int o = 16; o; o >>= 1) d += __shfl_xor_sync(0xffffffffu, d, o);
    float p0 = e0 / d, p1 = e1 / d;

    float mx = fmaxf(p0, p1);
#pragma unroll
    for (int o = 16; o; o >>= 1) mx = fmaxf(mx, __shfl_xor_sync(0xffffffffu, mx, o));
    int cand = 0x7fffffff;
    if (p0 == mx) cand = lane;
    if (p1 == mx) cand = min(cand, lane + 32);
#pragma unroll
    for (int o = 16; o; o >>= 1) cand = min(cand, __shfl_xor_sync(0xffffffffu, cand, o));
    int i1 = cand; float v1 = mx;

    float q0 = (lane == i1) ? -1e30f : p0;
    float q1 = (lane + 32 == i1) ? -1e30f : p1;
    float mx2 = fmaxf(q0, q1);
#pragma unroll
    for (int o = 16; o; o >>= 1) mx2 = fmaxf(mx2, __shfl_xor_sync(0xffffffffu, mx2, o));
    int cand2 = 0x7fffffff;
    if (q0 == mx2) cand2 = lane;
    if (q1 == mx2) cand2 = min(cand2, lane + 32);
#pragma unroll
    for (int o = 16; o; o >>= 1) cand2 = min(cand2, __shfl_xor_sync(0xffffffffu, cand2, o));
    int i2 = cand2; float v2 = mx2;

    if (lane == 0) {
        g_topi[t * 2 + 0] = i1; g_topv[t * 2 + 0] = v1;
        g_topi[t * 2 + 1] = i2; g_topv[t * 2 + 1] = v2;
        atomicAdd(&g_counts[i1], 1);
        atomicAdd(&g_counts[i2], 1);
    }
    atomicAdd(&g_psum[lane], p0);
    atomicAdd(&g_psum[lane + 32], p1);
}

// ---------------- build per-expert slot lists ----------------
__global__ void build_kernel() {
    int a = blockIdx.x * blockDim.x + threadIdx.x;
    if (a >= NASSIGN) return;
    int e = g_topi[a];
    int pos = atomicAdd(&g_listcnt[e], 1);
    if (pos < CAP) g_assign[e * CAP + pos] = a;
}

// ---------------- fp16 single-pass mma.sync GEMM ----------------
// C[M,N] = A[M,K] @ B[K,N]   (B row-major [K][N], loaded via ldmatrix.trans)
// CTA 128x128, K-chunk 64, 3-stage cp.async pipeline, 8 warps (warp tile 64x32).
// EPI: 0 = gelu -> fp16 out, 1 = f32 store, 2 = atomic combine into out[token]
#define STAGE_BYTES 32768   // A 16K + B 16K
#define MISC_OFF    98304   // 3 stages

template<int EPI, bool GATHER, bool EXPERT>
__global__ void __launch_bounds__(256, 2)
mma_gemm(const __half* __restrict__ A, int lda, long aBatch,
         const __half* __restrict__ B, int ldb, long bBatch,
         __half* __restrict__ outH, float* __restrict__ outF, int ldc, long cBatch,
         int M, int Kd)
{
    extern __shared__ char smem[];
    const int tid = threadIdx.x;
    const int lane = tid & 31, warp = tid >> 5;
    const int wm = warp & 1, wn = warp >> 1;
    const int bm = blockIdx.y * 128, bn = blockIdx.x * 128;

    int e = 0, cnt = M;
    if (EXPERT) {
        e = blockIdx.z;
        cnt = min(g_listcnt[e], CAP);
        if (bm >= cnt) return;
        if (aBatch) A += (size_t)e * aBatch;
        B += (size_t)e * bBatch;
        if (EPI == 0) outH += (size_t)e * cBatch;
    }

    int*   tok = (int*)(smem + MISC_OFF);
    float* pw  = (float*)(smem + MISC_OFF + 512);
    if ((GATHER || EPI == 2) && tid < 128) {
        int idx = min(bm + tid, cnt - 1);
        int a = g_assign[e * CAP + idx];
        tok[tid] = a >> 1;                    // token (KTOP=2)
        pw[tid]  = g_topv[a];
    }
    __syncthreads();

    uint32_t sb = smem_u32(smem);
    const int NC = Kd >> 6;

#define ISSUE_CHUNK(cc, ss) do {                                              \
    int k0_ = (cc) * 64;                                                      \
    uint32_t st_ = sb + (ss) * STAGE_BYTES;                                   \
    for (int p = tid; p < 1024; p += 256) {       /* A: 128 x 64 fp16 */      \
        int r_ = p >> 3, q_ = p & 7;                                          \
        size_t row_ = GATHER ? (size_t)tok[r_] : (size_t)(bm + r_);           \
        cp16(st_ + SWA((uint32_t)(r_ * 128 + q_ * 16)),                       \
             A + row_ * lda + k0_ + q_ * 8);                                  \
    }                                                                         \
    for (int p = tid; p < 1024; p += 256) {       /* B: 64 x 128 fp16 */      \
        int kr_ = p >> 4, nq_ = p & 15;                                       \
        cp16(st_ + 16384 + SWB((uint32_t)(kr_ * 256 + nq_ * 16)),             \
             B + (size_t)(k0_ + kr_) * ldb + bn + nq_ * 8);                   \
    } } while (0)

    ISSUE_CHUNK(0, 0); CP_COMMIT();
    ISSUE_CHUNK(1, 1); CP_COMMIT();

    float acc[4][4][4];
#pragma unroll
    for (int a = 0; a < 4; a++)
#pragma unroll
        for (int b = 0; b < 4; b++)
#pragma unroll
            for (int c = 0; c < 4; c++) acc[a][b][c] = 0.0f;

    for (int c = 0; c < NC; ++c) {
        CP_WAIT1();
        __syncthreads();
        if (c + 2 < NC) { ISSUE_CHUNK(c + 2, (c + 2) % 3); }
        CP_COMMIT();
        uint32_t sA = sb + (c % 3) * STAGE_BYTES;
        uint32_t sB = sA + 16384;
#pragma unroll
        for (int kk = 0; kk < 4; kk++) {
            uint32_t af[4][4];
#pragma unroll
            for (int mt = 0; mt < 4; mt++) {
                uint32_t off = SWA((uint32_t)((wm * 64 + mt * 16 + (lane & 15)) * 128
                                              + kk * 32 + ((lane >> 4) << 4)));
                ldm_x4(sA + off, af[mt][0], af[mt][1], af[mt][2], af[mt][3]);
            }
#pragma unroll
            for (int ntp = 0; ntp < 2; ntp++) {
                uint32_t boff = SWB((uint32_t)((kk * 16 + (lane & 15)) * 256
                                + (wn * 32 + ntp * 16 + ((lane >> 4) << 3)) * 2));
                uint32_t b0, b1, b2, b3;
                ldm_x4t(sB + boff, b0, b1, b2, b3);
#pragma unroll
                for (int mt = 0; mt < 4; mt++) {
                    mma_fp16(acc[mt][ntp * 2],     af[mt], b0, b1);
                    mma_fp16(acc[mt][ntp * 2 + 1], af[mt], b2, b3);
                }
            }
        }
    }
#undef ISSUE_CHUNK

    const int gr = lane >> 2, gc = (lane & 3) * 2;
    if (EPI == 2) {
        __syncthreads();   // all warps done with smem stages before tile reuse
        float* tile = (float*)smem;   // 128x128 f32 = 64KB
#pragma unroll
        for (int mt = 0; mt < 4; mt++)
#pragma unroll
            for (int nt = 0; nt < 4; nt++)
#pragma unroll
                for (int h = 0; h < 2; h++) {
                    int rl = wm * 64 + mt * 16 + gr + h * 8;
                    int cl = wn * 32 + nt * 8 + gc;
                    *reinterpret_cast<float2*>(&tile[rl * 128 + cl]) =
                        make_float2(acc[mt][nt][2 * h], acc[mt][nt][2 * h + 1]);
                }
        __syncthreads();
        for (int r = warp; r < 128; r += 8) {
            if (bm + r < cnt) {
                float p = pw[r];
                float* base = outF + (size_t)tok[r] * HID + bn;
                for (int cc = lane; cc < 128; cc += 32)
                    atomicAdd(base + cc, p * tile[r * 128 + cc]);
            }
        }
    } else {
#pragma unroll
        for (int mt = 0; mt < 4; mt++)
#pragma unroll
            for (int nt = 0; nt < 4; nt++)
#pragma unroll
                for (int h = 0; h < 2; h++) {
                    int r = bm + wm * 64 + mt * 16 + gr + h * 8;
                    if (r >= cnt) continue;
                    int col = bn + wn * 32 + nt * 8 + gc;
                    if (EPI == 0) {
                        __half2 hv = __floats2half2_rn(gelu_f(acc[mt][nt][2 * h]),
                                                       gelu_f(acc[mt][nt][2 * h + 1]));
                        *reinterpret_cast<__half2*>(outH + (size_t)r * ldc + col) = hv;
                    } else {
                        *reinterpret_cast<float2*>(outF + (size_t)r * ldc + col) =
                            make_float2(acc[mt][nt][2 * h], acc[mt][nt][2 * h + 1]);
                    }
                }
    }
}

// ---------------- aux loss ----------------
__global__ void aux_kernel(float* __restrict__ out, int out_size)
{
    __shared__ float vals[NEXP];
    int i = threadIdx.x;
    if (i < NEXP) {
        float f = (float)g_counts[i] / (float)(T_TOK * KTOP);
        float P = g_psum[i] / (float)T_TOK;
        vals[i] = f * P;
    }
    __syncthreads();
    if (i == 0) {
        float s = 0.0f;
        for (int j = 0; j < NEXP; j++) s += vals[j];
        if (out_size > T_TOK * HID) out[T_TOK * HID] = 0.01f * (float)NEXP * s;
    }
}

// ---------------- launch ----------------
extern "C" void kernel_launch(void* const* d_in, const int* in_sizes, int n_in,
                              void* d_out, int out_size)
{
    const float* x        = (const float*)d_in[0];  // [T,H]
    const float* w_router = (const float*)d_in[1];  // [H,E]
    const float* w1       = (const float*)d_in[2];  // [E,H,F]
    const float* w2       = (const float*)d_in[3];  // [E,F,H]
    const float* ws1      = (const float*)d_in[4];  // [H,SF]
    const float* ws2      = (const float*)d_in[5];  // [SF,H]
    float* out = (float*)d_out;

    float* logits; cudaGetSymbolAddress((void**)&logits, g_logits);
    __half *xh, *w1h, *w2h, *ws1h, *ws2h, *hbuf, *sbuf;
    cudaGetSymbolAddress((void**)&xh,  g_xh);
    cudaGetSymbolAddress((void**)&w1h, g_w1h);
    cudaGetSymbolAddress((void**)&w2h, g_w2h);
    cudaGetSymbolAddress((void**)&ws1h, g_ws1h);
    cudaGetSymbolAddress((void**)&ws2h, g_ws2h);
    cudaGetSymbolAddress((void**)&hbuf, g_h);
    cudaGetSymbolAddress((void**)&sbuf, g_s);

    const int SMB = MISC_OFF + 1024;   // 3 stages + tok/pw
    cudaFuncSetAttribute(mma_gemm<0, true,  true >, cudaFuncAttributeMaxDynamicSharedMemorySize, SMB);
    cudaFuncSetAttribute(mma_gemm<2, false, true >, cudaFuncAttributeMaxDynamicSharedMemorySize, SMB);
    cudaFuncSetAttribute(mma_gemm<0, false, false>, cudaFuncAttributeMaxDynamicSharedMemorySize, SMB);
    cudaFuncSetAttribute(mma_gemm<1, false, false>, cudaFuncAttributeMaxDynamicSharedMemorySize, SMB);

    // ---- prepass conversions ----
    cvt1<<<1024, 256>>>(x, xh, T_TOK * HID);
    cvt1<<<4096, 256>>>(w1, w1h, NEXP * HID * FFN);
    cvt1<<<4096, 256>>>(w2, w2h, NEXP * FFN * HID);
    cvt1<<<512, 256>>>(ws1, ws1h, HID * SFFN);
    cvt1<<<512, 256>>>(ws2, ws2h, SFFN * HID);

    zero_kernel<<<1, 256>>>();

    // ---- router (exact fp32) + routing ----
    router_sgemm<<<dim3(1, T_TOK / RTM), 256>>>(x, w_router, logits);
    topk_kernel<<<T_TOK / 4, 128>>>();
    build_kernel<<<(NASSIGN + 255) / 256, 256>>>();

    // ---- shared expert (writes base of out) ----
    mma_gemm<0, false, false><<<dim3(SFFN / 128, T_TOK / 128), 256, SMB>>>(
        xh, HID, 0, ws1h, SFFN, 0, sbuf, nullptr, SFFN, 0, T_TOK, HID);
    mma_gemm<1, false, false><<<dim3(HID / 128, T_TOK / 128), 256, SMB>>>(
        sbuf, SFFN, 0, ws2h, HID, 0, nullptr, out, HID, 0, T_TOK, SFFN);

    // ---- expert MLP; gemm2 atomically combines into out ----
    mma_gemm<0, true, true><<<dim3(FFN / 128, CAP / 128, NEXP), 256, SMB>>>(
        xh, HID, 0, w1h, FFN, (long)HID * FFN, hbuf, nullptr, FFN, (long)CAP * FFN,
        CAP, HID);
    mma_gemm<2, false, true><<<dim3(HID / 128, CAP / 128, NEXP), 256, SMB>>>(
        hbuf, FFN, (long)CAP * FFN, w2h, HID, (long)FFN * HID,
        nullptr, out, HID, 0, CAP, FFN);

    aux_kernel<<<1, 64>>>(out, out_size);
}